// round 13
// baseline (speedup 1.0000x reference)
#include <cuda_runtime.h>
#include <cuda_fp16.h>
#include <cstdint>
#include <math.h>

#define D_DIM 1024
#define H_DIM 512
#define E_NUM 16
#define NTOK  4096
#define KSEL  8
#define NK    (NTOK * KSEL)

// ---------------------------------------------------------------------------
// Device scratch
// ---------------------------------------------------------------------------
__device__ float g_gwn[E_NUM * D_DIM];
__device__ int   g_idx[NK];
__device__ float g_w[NK];
__device__ int   g_cnt[E_NUM];
__device__ int   g_pos[E_NUM];
__device__ int   g_tok[NK + 128];
__device__ float g_tw[NK + 128];
__device__ int   g_pmap[NK];

__device__ __half g_xt[(size_t)NTOK * D_DIM];                // fp16 x
__device__ __half g_wguT[(size_t)E_NUM * 2 * H_DIM * D_DIM]; // [E][2H][D] interleaved gate/up
__device__ __half g_wdT [(size_t)E_NUM * D_DIM * H_DIM];     // [E][D][H]
__device__ __half g_swguT[(size_t)2 * H_DIM * D_DIM];
__device__ __half g_swdT [(size_t)D_DIM * H_DIM];

__device__ __half g_h [((size_t)NK + 128) * H_DIM];          // routed hidden (weighted)
__device__ __half g_hs[(size_t)NTOK * H_DIM];                // shared hidden
__device__ __half g_yh[(size_t)NK * D_DIM];                  // routed down output (fp16)

// ---------------------------------------------------------------------------
// Helpers (sm_80-compatible PTX only — harness compiles for plain sm_100)
// ---------------------------------------------------------------------------
__device__ __forceinline__ uint32_t smem_u32(const void* p) {
    uint32_t a;
    asm("{ .reg .u64 t; cvta.to.shared.u64 t, %1; cvt.u32.u64 %0, t; }" : "=r"(a) : "l"(p));
    return a;
}
__device__ __forceinline__ void cp16(uint32_t dst, const void* src) {
    asm volatile("cp.async.cg.shared.global [%0], [%1], 16;" :: "r"(dst), "l"(src));
}
#define CP_COMMIT() asm volatile("cp.async.commit_group;" ::: "memory")
#define CP_WAIT1()  asm volatile("cp.async.wait_group 1;" ::: "memory")

__device__ __forceinline__ void ldm4(uint32_t& r0, uint32_t& r1, uint32_t& r2, uint32_t& r3,
                                     uint32_t a) {
    asm volatile("ldmatrix.sync.aligned.m8n8.x4.shared.b16 {%0,%1,%2,%3}, [%4];"
                 : "=r"(r0), "=r"(r1), "=r"(r2), "=r"(r3) : "r"(a));
}
__device__ __forceinline__ void mma16(float* c, const uint32_t* a, uint32_t b0, uint32_t b1) {
    asm volatile("mma.sync.aligned.m16n8k16.row.col.f32.f16.f16.f32 "
                 "{%0,%1,%2,%3}, {%4,%5,%6,%7}, {%8,%9}, {%0,%1,%2,%3};"
                 : "+f"(c[0]), "+f"(c[1]), "+f"(c[2]), "+f"(c[3])
                 : "r"(a[0]), "r"(a[1]), "r"(a[2]), "r"(a[3]), "r"(b0), "r"(b1));
}

// ---------------------------------------------------------------------------
// gwnorm: small, must precede gating. Also zeroes counters.
// ---------------------------------------------------------------------------
__global__ void gwnorm_kernel(const float* __restrict__ gw) {
    int e = blockIdx.x, t = threadIdx.x;
    if (e == 0 && t < E_NUM) { g_cnt[t] = 0; g_pos[t] = 0; }
    __shared__ float red[8];
    float ss = 0.f;
    for (int i = t; i < D_DIM; i += 256) { float v = gw[e * D_DIM + i]; ss += v * v; }
    for (int o = 16; o; o >>= 1) ss += __shfl_down_sync(0xFFFFFFFFu, ss, o);
    if ((t & 31) == 0) red[t >> 5] = ss;
    __syncthreads();
    __shared__ float s_inv;
    if (t == 0) {
        float tot = 0.f;
        for (int i = 0; i < 8; i++) tot += red[i];
        s_inv = 1.0f / fmaxf(sqrtf(tot), 1e-12f);
    }
    __syncthreads();
    float inv = s_inv;
    for (int i = t; i < D_DIM; i += 256) g_gwn[e * D_DIM + i] = gw[e * D_DIM + i] * inv;
}

// ---------------------------------------------------------------------------
// fused gating + weight-prep: flat 1D grid (same as R12).
// ---------------------------------------------------------------------------
__global__ void fused_pg_kernel(const float* __restrict__ x,
                                const float* __restrict__ wg, const float* __restrict__ wu,
                                const float* __restrict__ wd, const float* __restrict__ swg,
                                const float* __restrict__ swu, const float* __restrict__ swd,
                                __half* __restrict__ wguT, __half* __restrict__ wdT,
                                __half* __restrict__ swguT, __half* __restrict__ swdT) {
    const int bid = blockIdx.x;
    const int t = threadIdx.x;

    if (bid < NTOK) {
        const int n = bid;
        const int warp = t >> 5, lane = t & 31;
        __shared__ float sx[D_DIM];
        __shared__ float red[8];
        __shared__ float slog[E_NUM];
        const float* xr = x + (size_t)n * D_DIM;
        float ss = 0.f;
        for (int i = t; i < D_DIM; i += 256) { float v = xr[i]; sx[i] = v; ss += v * v; }
        for (int o = 16; o; o >>= 1) ss += __shfl_down_sync(0xFFFFFFFFu, ss, o);
        if (lane == 0) red[warp] = ss;
        __syncthreads();
        for (int i = t; i < D_DIM; i += 256) g_xt[(size_t)n * D_DIM + i] = __float2half_rn(sx[i]);
        for (int j = 0; j < 2; j++) {
            int e = warp * 2 + j;
            const float* g = g_gwn + e * D_DIM;
            float d = 0.f;
            for (int i = lane; i < D_DIM; i += 32) d += sx[i] * g[i];
            for (int o = 16; o; o >>= 1) d += __shfl_down_sync(0xFFFFFFFFu, d, o);
            if (lane == 0) slog[e] = d;
        }
        __syncthreads();
        if (t == 0) {
            float ssq = 0.f;
            for (int i = 0; i < 8; i++) ssq += red[i];
            float inv = 1.0f / fmaxf(sqrtf(ssq), 1e-12f);
            float sc[E_NUM];
            for (int e = 0; e < E_NUM; e++) sc[e] = slog[e] * inv;
            int sel[KSEL]; float sw[KSEL]; float wsum = 0.f;
            for (int k = 0; k < KSEL; k++) {
                int bi = 0; float bv = -1e30f;
                for (int e = 0; e < E_NUM; e++)
                    if (sc[e] > bv) { bv = sc[e]; bi = e; }
                sel[k] = bi;
                float s = 1.0f / (1.0f + __expf(-bv));
                sw[k] = s; wsum += s; sc[bi] = -1e30f;
            }
            float invw = 1.0f / wsum;
            for (int k = 0; k < KSEL; k++) {
                g_idx[n * KSEL + k] = sel[k];
                g_w[n * KSEL + k]   = sw[k] * invw;
                atomicAdd(&g_cnt[sel[k]], 1);
            }
        }
        return;
    }

    const int p = bid - NTOK;
    const int z = p >> 9;
    const int xt_ = p & 31;
    const int yt_ = (p >> 5) & 15;
    const int tx = t & 31, ty = t >> 5;

    const float* src; __half* dst;
    int R, C, mul, add;
    size_t bi, bo;
    if (z < 16)       { int e = z;      src = wg;  dst = wguT;  R = D_DIM; C = H_DIM; mul = 2; add = 0; bi = (size_t)e * R * C; bo = bi * 2; }
    else if (z < 32)  { int e = z - 16; src = wu;  dst = wguT;  R = D_DIM; C = H_DIM; mul = 2; add = 1; bi = (size_t)e * R * C; bo = bi * 2; }
    else if (z < 48)  { int e = z - 32; src = wd;  dst = wdT;   R = H_DIM; C = D_DIM; mul = 1; add = 0; bi = (size_t)e * R * C; bo = bi; }
    else if (z == 48) { src = swg; dst = swguT; R = D_DIM; C = H_DIM; mul = 2; add = 0; bi = 0; bo = 0; }
    else if (z == 49) { src = swu; dst = swguT; R = D_DIM; C = H_DIM; mul = 2; add = 1; bi = 0; bo = 0; }
    else              { src = swd; dst = swdT;  R = H_DIM; C = D_DIM; mul = 1; add = 0; bi = 0; bo = 0; }

    const int c0 = xt_ * 32, r0 = yt_ * 64;
    if (c0 >= C || r0 >= R) return;

    __shared__ float tile[32][65];
#pragma unroll
    for (int j = 0; j < 64; j += 8)
        tile[tx][ty + j] = src[bi + (size_t)(r0 + ty + j) * C + c0 + tx];
    __syncthreads();
#pragma unroll
    for (int jc = 0; jc < 4; jc++) {
        int c = ty + jc * 8;
        __half2 v = __floats2half2_rn(tile[c][2 * tx], tile[c][2 * tx + 1]);
        *(__half2*)(dst + bo + (size_t)((c0 + c) * mul + add) * R + r0 + 2 * tx) = v;
    }
}

// scatter with in-block prefix over g_cnt
__global__ void scatter_kernel() {
    __shared__ int soff[E_NUM];
    int t = threadIdx.x;
    if (t == 0) {
        int a = 0;
        for (int e = 0; e < E_NUM; e++) { soff[e] = a; a += g_cnt[e]; }
    }
    __syncthreads();
    int id = blockIdx.x * 256 + t;
    if (id < NK) {
        int e = g_idx[id];
        int p = soff[e] + atomicAdd(&g_pos[e], 1);
        g_tok[p] = id / KSEL;
        g_tw[p]  = g_w[id];
        g_pmap[id] = p;
    }
}

// ---------------------------------------------------------------------------
// fp16 mma.sync GEMM: BM=128, BN=64, BK=64, 8 warps 4(m)x2(n),
// warp tile 32x32 -> 32 fp32 accums/thread. Frees registers for a
// ks-level fragment PING-PONG (LDSM for ks+1 issued before ks's HMMAs),
// attacking the per-warp LDSM->HMMA dependency that pins tensor at ~52%.
// 3-stage cp.async, 2 CTAs/SM. z<16 routed expert z, z==16 shared.
// ---------------------------------------------------------------------------
#define ROWB    144
#define A_ST    (128 * ROWB)      // 18432 B
#define B_ST    (64 * ROWB)       // 9216 B
#define NSTG    3
#define SMEM_BYTES (NSTG * (A_ST + B_ST) + 1024)

template <bool GU>
__global__ void __launch_bounds__(256)
mma_gemm(const __half* __restrict__ Art, const __half* __restrict__ Ash,
         const __half* __restrict__ Brt, const __half* __restrict__ Bsh,
         __half* __restrict__ outRt, void* __restrict__ outShv) {
    constexpr int KD = GU ? D_DIM : H_DIM;
    const int e = blockIdx.z;
    const bool gather = (e < E_NUM);
    const int cnt = gather ? g_cnt[e] : NTOK;
    const int m0  = blockIdx.x * 128;
    if (m0 >= cnt) return;
    int offr = 0;
    if (gather) {
        for (int q = 0; q < E_NUM; q++) offr += (q < e) ? g_cnt[q] : 0;
    }
    const int n0 = blockIdx.y * 64;

    const __half* A = gather ? Art : Ash;
    const __half* B = gather ? (Brt + (size_t)e * 1024 * KD) : Bsh;

    extern __shared__ char smc[];
    const uint32_t uA = smem_u32(smc);
    const uint32_t uB = uA + NSTG * A_ST;
    int*   rtok = (int*)(smc + NSTG * (A_ST + B_ST));
    float* twsh = (float*)(smc + NSTG * (A_ST + B_ST) + 512);

    const int t = threadIdx.x;
    const int warp = t >> 5, lane = t & 31;
    const int wm = warp >> 1, wn = warp & 1;    // 4(m) x 2(n)

    if (t < 128) {
        int gm = m0 + t;
        int cg = (gm < cnt) ? gm : 0;
        int src;
        if (GU) src = gather ? g_tok[offr + cg] : gm;
        else    src = gather ? (offr + gm) : gm;
        rtok[t] = src;
        twsh[t] = (GU && gather) ? g_tw[offr + cg] : 1.0f;
    }
    __syncthreads();

    // loader map: A 4 chunks (128 rows x 8 kc / 256 thr), B 2 chunks (64 rows)
    const __half* aP[4];
    const __half* bP[2];
    uint32_t aO[4], bO[2];
#pragma unroll
    for (int j = 0; j < 4; j++) {
        int cidx = t + j * 256;
        int row = cidx >> 3, kc = cidx & 7;
        aP[j] = A + (size_t)rtok[row] * KD + kc * 8;
        aO[j] = (uint32_t)(row * ROWB + kc * 16);
    }
#pragma unroll
    for (int j = 0; j < 2; j++) {
        int cidx = t + j * 256;
        int row = cidx >> 3, kc = cidx & 7;
        bP[j] = B + (size_t)(n0 + row) * KD + kc * 8;
        bO[j] = (uint32_t)(row * ROWB + kc * 16);
    }

    // ks-invariant ldsm address parts
    const uint32_t aRow = wm * 32 + (lane & 7) + ((lane >> 3) & 1) * 8;
    const uint32_t aCol = (lane >> 4) * 16;
    const uint32_t bRow0 = wn * 32 + ((lane >> 4) & 1) * 8 + (lane & 7);
    const uint32_t bCol = ((lane >> 3) & 1) * 16;

#define LOADSTAGE(s, k0) do {                                       \
        _Pragma("unroll")                                           \
        for (int j = 0; j < 4; j++)                                 \
            cp16(uA + (s) * A_ST + aO[j], aP[j] + (k0));            \
        _Pragma("unroll")                                           \
        for (int j = 0; j < 2; j++)                                 \
            cp16(uB + (s) * B_ST + bO[j], bP[j] + (k0));            \
    } while (0)

#define LOADFRAG(q, uAs, uBs, ks) do {                                            \
        _Pragma("unroll")                                                         \
        for (int mt = 0; mt < 2; mt++) {                                          \
            uint32_t ad = (uAs) + (aRow + mt * 16) * ROWB + (ks) * 32 + aCol;     \
            ldm4(afr[q][mt][0], afr[q][mt][1], afr[q][mt][2], afr[q][mt][3], ad); \
        }                                                                         \
        _Pragma("unroll")                                                         \
        for (int p = 0; p < 2; p++) {                                             \
            uint32_t ad = (uBs) + (bRow0 + p * 16) * ROWB + (ks) * 32 + bCol;     \
            ldm4(bfr[q][p][0], bfr[q][p][1], bfr[q][p][2], bfr[q][p][3], ad);     \
        }                                                                         \
    } while (0)

    float c[2][4][4] = {};
    uint32_t afr[2][2][4], bfr[2][2][4];

    const int NIT = KD / 64;
    LOADSTAGE(0, 0);  CP_COMMIT();
    LOADSTAGE(1, 64); CP_COMMIT();

    for (int i = 0; i < NIT; i++) {
        CP_WAIT1();
        __syncthreads();
        const int ld = i + 2;
        if (ld < NIT) LOADSTAGE(ld % NSTG, ld * 64);
        CP_COMMIT();

        const int s = i % NSTG;
        const uint32_t uAs = uA + s * A_ST;
        const uint32_t uBs = uB + s * B_ST;

        LOADFRAG(0, uAs, uBs, 0);
#pragma unroll
        for (int j = 0; j < 4; j++) {
            const int cur = j & 1;
            if (j < 3) LOADFRAG(cur ^ 1, uAs, uBs, j + 1);
#pragma unroll
            for (int mt = 0; mt < 2; mt++) {
#pragma unroll
                for (int nt = 0; nt < 4; nt++)
                    mma16(c[mt][nt], afr[cur][mt],
                          bfr[cur][nt >> 1][2 * (nt & 1)], bfr[cur][nt >> 1][2 * (nt & 1) + 1]);
            }
        }
    }
#undef LOADSTAGE
#undef LOADFRAG

#pragma unroll
    for (int mt = 0; mt < 2; mt++) {
        int r0 = wm * 32 + mt * 16 + (lane >> 2);
#pragma unroll
        for (int pass = 0; pass < 2; pass++) {
            int r = r0 + pass * 8;
            int gm = m0 + r;
            if (gm < cnt) {
                if (GU) {
                    float tw = twsh[r];
                    __half* orow = (gather ? outRt + (size_t)(offr + gm) * H_DIM
                                           : (__half*)outShv + (size_t)gm * H_DIM);
#pragma unroll
                    for (int nt = 0; nt < 4; nt++) {
                        float g = c[mt][nt][pass * 2];
                        float u = c[mt][nt][pass * 2 + 1];
                        int h = (n0 + wn * 32 + nt * 8) / 2 + (lane & 3);
                        orow[h] = __float2half_rn(tw * u * g / (1.0f + __expf(-g)));
                    }
                } else if (gather) {
                    __half* orow = outRt + (size_t)(offr + gm) * D_DIM;
#pragma unroll
                    for (int nt = 0; nt < 4; nt++) {
                        int n = n0 + wn * 32 + nt * 8 + 2 * (lane & 3);
                        *(__half2*)(orow + n) =
                            __floats2half2_rn(c[mt][nt][pass * 2], c[mt][nt][pass * 2 + 1]);
                    }
                } else {
                    float* orow = (float*)outShv + (size_t)gm * D_DIM;
#pragma unroll
                    for (int nt = 0; nt < 4; nt++) {
                        int n = n0 + wn * 32 + nt * 8 + 2 * (lane & 3);
                        *(float2*)(orow + n) =
                            make_float2(c[mt][nt][pass * 2], c[mt][nt][pass * 2 + 1]);
                    }
                }
            }
        }
    }
}

// ---------------------------------------------------------------------------
// combine: out[n] (shared result) += sum_k g_yh[pmap[n,k]]  (fp16 reads)
// ---------------------------------------------------------------------------
__global__ void combine_kernel(float* __restrict__ out) {
    const int n = blockIdx.x, t = threadIdx.x;
    __shared__ int pm[KSEL];
    if (t < KSEL) pm[t] = g_pmap[n * KSEL + t];
    __syncthreads();
    float4 acc = *(const float4*)(out + (size_t)n * D_DIM + t * 4);
#pragma unroll
    for (int k = 0; k < KSEL; k++) {
        const __half2* p = (const __half2*)(g_yh + (size_t)pm[k] * D_DIM + t * 4);
        float2 v0 = __half22float2(p[0]);
        float2 v1 = __half22float2(p[1]);
        acc.x += v0.x; acc.y += v0.y; acc.z += v1.x; acc.w += v1.y;
    }
    *(float4*)(out + (size_t)n * D_DIM + t * 4) = acc;
}

// ---------------------------------------------------------------------------
// Launch:  gwnorm(1) fused_pg(2) scatter(3) GU(4) DN(5) combine(6)
// ---------------------------------------------------------------------------
extern "C" void kernel_launch(void* const* d_in, const int* in_sizes, int n_in,
                              void* d_out, int out_size) {
    (void)in_sizes; (void)n_in; (void)out_size;
    const float* x       = (const float*)d_in[0];
    const float* gate_w  = (const float*)d_in[1];
    const float* w_gate  = (const float*)d_in[2];
    const float* w_up    = (const float*)d_in[3];
    const float* w_down  = (const float*)d_in[4];
    const float* sw_gate = (const float*)d_in[5];
    const float* sw_up   = (const float*)d_in[6];
    const float* sw_down = (const float*)d_in[7];
    float* out = (float*)d_out;

    cudaFuncSetAttribute(mma_gemm<true>,  cudaFuncAttributeMaxDynamicSharedMemorySize, SMEM_BYTES);
    cudaFuncSetAttribute(mma_gemm<false>, cudaFuncAttributeMaxDynamicSharedMemorySize, SMEM_BYTES);

    __half* xt; __half* wguT; __half* wdT; __half* swguT; __half* swdT;
    __half* hbuf; __half* hsbuf; __half* ybuf;
    cudaGetSymbolAddress((void**)&xt,    g_xt);
    cudaGetSymbolAddress((void**)&wguT,  g_wguT);
    cudaGetSymbolAddress((void**)&wdT,   g_wdT);
    cudaGetSymbolAddress((void**)&swguT, g_swguT);
    cudaGetSymbolAddress((void**)&swdT,  g_swdT);
    cudaGetSymbolAddress((void**)&hbuf,  g_h);
    cudaGetSymbolAddress((void**)&hsbuf, g_hs);
    cudaGetSymbolAddress((void**)&ybuf,  g_yh);

    gwnorm_kernel<<<E_NUM, 256>>>(gate_w);

    fused_pg_kernel<<<NTOK + 51 * 512, 256>>>(
        x, w_gate, w_up, w_down, sw_gate, sw_up, sw_down, wguT, wdT, swguT, swdT);

    scatter_kernel<<<(NK + 255) / 256, 256>>>();

    // GU: routed (z<16) + shared (z==16); BN=64 -> 16 n-tiles
    mma_gemm<true><<<dim3(32, 16, E_NUM + 1), 256, SMEM_BYTES>>>(
        xt, xt, wguT, swguT, hbuf, (void*)hsbuf);

    // DN: routed -> g_yh (fp16), shared -> out (fp32); BN=64 -> 16 n-tiles
    mma_gemm<false><<<dim3(32, 16, E_NUM + 1), 256, SMEM_BYTES>>>(
        hbuf, hsbuf, wdT, swdT, ybuf, (void*)out);

    combine_kernel<<<NTOK, 256>>>(out);
}

// round 14
// speedup vs baseline: 1.1752x; 1.1752x over previous
#include <cuda_runtime.h>
#include <cuda_fp16.h>
#include <cstdint>
#include <math.h>

#define D_DIM 1024
#define H_DIM 512
#define E_NUM 16
#define NTOK  4096
#define KSEL  8
#define NK    (NTOK * KSEL)

// ---------------------------------------------------------------------------
// Device scratch
// ---------------------------------------------------------------------------
__device__ float g_gwn[E_NUM * D_DIM];
__device__ int   g_idx[NK];
__device__ float g_w[NK];
__device__ int   g_cnt[E_NUM];
__device__ int   g_pos[E_NUM];
__device__ int   g_tok[NK + 128];
__device__ float g_tw[NK + 128];
__device__ int   g_pmap[NK];

__device__ __half g_xt[(size_t)NTOK * D_DIM];                // fp16 x
__device__ __half g_wguT[(size_t)E_NUM * 2 * H_DIM * D_DIM]; // [E][2H][D] interleaved gate/up
__device__ __half g_wdT [(size_t)E_NUM * D_DIM * H_DIM];     // [E][D][H]
__device__ __half g_swguT[(size_t)2 * H_DIM * D_DIM];
__device__ __half g_swdT [(size_t)D_DIM * H_DIM];

__device__ __half g_h [((size_t)NK + 128) * H_DIM];          // routed hidden (weighted)
__device__ __half g_hs[(size_t)NTOK * H_DIM];                // shared hidden
__device__ __half g_yh[(size_t)NK * D_DIM];                  // routed down output (fp16)

// ---------------------------------------------------------------------------
// Helpers (sm_80-compatible PTX only — harness compiles for plain sm_100)
// ---------------------------------------------------------------------------
__device__ __forceinline__ uint32_t smem_u32(const void* p) {
    uint32_t a;
    asm("{ .reg .u64 t; cvta.to.shared.u64 t, %1; cvt.u32.u64 %0, t; }" : "=r"(a) : "l"(p));
    return a;
}
__device__ __forceinline__ void cp16(uint32_t dst, const void* src) {
    asm volatile("cp.async.cg.shared.global [%0], [%1], 16;" :: "r"(dst), "l"(src));
}
#define CP_COMMIT() asm volatile("cp.async.commit_group;" ::: "memory")
#define CP_WAIT1()  asm volatile("cp.async.wait_group 1;" ::: "memory")

__device__ __forceinline__ void ldm4(uint32_t& r0, uint32_t& r1, uint32_t& r2, uint32_t& r3,
                                     uint32_t a) {
    asm volatile("ldmatrix.sync.aligned.m8n8.x4.shared.b16 {%0,%1,%2,%3}, [%4];"
                 : "=r"(r0), "=r"(r1), "=r"(r2), "=r"(r3) : "r"(a));
}
__device__ __forceinline__ void mma16(float* c, const uint32_t* a, uint32_t b0, uint32_t b1) {
    asm volatile("mma.sync.aligned.m16n8k16.row.col.f32.f16.f16.f32 "
                 "{%0,%1,%2,%3}, {%4,%5,%6,%7}, {%8,%9}, {%0,%1,%2,%3};"
                 : "+f"(c[0]), "+f"(c[1]), "+f"(c[2]), "+f"(c[3])
                 : "r"(a[0]), "r"(a[1]), "r"(a[2]), "r"(a[3]), "r"(b0), "r"(b1));
}

// shared 64r x 32c transpose-convert tile step (smem provided by caller)
__device__ __forceinline__ void tile_transpose(const float* src, __half* dst,
                                               int R, int C, int mul, int add,
                                               size_t bi, size_t bo,
                                               int c0, int r0, float* tile, int t) {
    const int tx = t & 31, ty = t >> 5;   // 32 x 8
#pragma unroll
    for (int j = 0; j < 64; j += 8)
        tile[tx * 65 + ty + j] = src[bi + (size_t)(r0 + ty + j) * C + c0 + tx];
    __syncthreads();
#pragma unroll
    for (int jc = 0; jc < 4; jc++) {
        int c = ty + jc * 8;
        __half2 v = __floats2half2_rn(tile[c * 65 + 2 * tx], tile[c * 65 + 2 * tx + 1]);
        *(__half2*)(dst + bo + (size_t)((c0 + c) * mul + add) * R + r0 + 2 * tx) = v;
    }
    __syncthreads();
}

// ---------------------------------------------------------------------------
// gwnorm: must precede gating. Also zeroes counters.
// ---------------------------------------------------------------------------
__global__ void gwnorm_kernel(const float* __restrict__ gw) {
    int e = blockIdx.x, t = threadIdx.x;
    if (e == 0 && t < E_NUM) { g_cnt[t] = 0; g_pos[t] = 0; }
    __shared__ float red[8];
    float ss = 0.f;
    for (int i = t; i < D_DIM; i += 256) { float v = gw[e * D_DIM + i]; ss += v * v; }
    for (int o = 16; o; o >>= 1) ss += __shfl_down_sync(0xFFFFFFFFu, ss, o);
    if ((t & 31) == 0) red[t >> 5] = ss;
    __syncthreads();
    __shared__ float s_inv;
    if (t == 0) {
        float tot = 0.f;
        for (int i = 0; i < 8; i++) tot += red[i];
        s_inv = 1.0f / fmaxf(sqrtf(tot), 1e-12f);
    }
    __syncthreads();
    float inv = s_inv;
    for (int i = t; i < D_DIM; i += 256) g_gwn[e * D_DIM + i] = gw[e * D_DIM + i] * inv;
}

// ---------------------------------------------------------------------------
// fused gating + GU-weight prep (wg/wu/swg/swu only; wd moved into GU launch).
//   bid < NTOK : gating for token bid (exact fp32; also emits g_xt fp16)
//   bid >= NTOK: transpose job p = bid - NTOK; z = p>>9 in 0..33
// ---------------------------------------------------------------------------
__global__ void fused_pg_kernel(const float* __restrict__ x,
                                const float* __restrict__ wg, const float* __restrict__ wu,
                                const float* __restrict__ swg, const float* __restrict__ swu,
                                __half* __restrict__ wguT, __half* __restrict__ swguT) {
    const int bid = blockIdx.x;
    const int t = threadIdx.x;

    if (bid < NTOK) {
        const int n = bid;
        const int warp = t >> 5, lane = t & 31;
        __shared__ float sx[D_DIM];
        __shared__ float red[8];
        __shared__ float slog[E_NUM];
        const float* xr = x + (size_t)n * D_DIM;
        float ss = 0.f;
        for (int i = t; i < D_DIM; i += 256) { float v = xr[i]; sx[i] = v; ss += v * v; }
        for (int o = 16; o; o >>= 1) ss += __shfl_down_sync(0xFFFFFFFFu, ss, o);
        if (lane == 0) red[warp] = ss;
        __syncthreads();
        for (int i = t; i < D_DIM; i += 256) g_xt[(size_t)n * D_DIM + i] = __float2half_rn(sx[i]);
        for (int j = 0; j < 2; j++) {
            int e = warp * 2 + j;
            const float* g = g_gwn + e * D_DIM;
            float d = 0.f;
            for (int i = lane; i < D_DIM; i += 32) d += sx[i] * g[i];
            for (int o = 16; o; o >>= 1) d += __shfl_down_sync(0xFFFFFFFFu, d, o);
            if (lane == 0) slog[e] = d;
        }
        __syncthreads();
        if (t == 0) {
            float ssq = 0.f;
            for (int i = 0; i < 8; i++) ssq += red[i];
            float inv = 1.0f / fmaxf(sqrtf(ssq), 1e-12f);
            float sc[E_NUM];
            for (int e = 0; e < E_NUM; e++) sc[e] = slog[e] * inv;
            int sel[KSEL]; float sw[KSEL]; float wsum = 0.f;
            for (int k = 0; k < KSEL; k++) {
                int bi = 0; float bv = -1e30f;
                for (int e = 0; e < E_NUM; e++)
                    if (sc[e] > bv) { bv = sc[e]; bi = e; }
                sel[k] = bi;
                float s = 1.0f / (1.0f + __expf(-bv));
                sw[k] = s; wsum += s; sc[bi] = -1e30f;
            }
            float invw = 1.0f / wsum;
            for (int k = 0; k < KSEL; k++) {
                g_idx[n * KSEL + k] = sel[k];
                g_w[n * KSEL + k]   = sw[k] * invw;
                atomicAdd(&g_cnt[sel[k]], 1);
            }
        }
        return;
    }

    const int p = bid - NTOK;
    const int z = p >> 9;
    const int ct = p & 31;
    const int rt = (p >> 5) & 15;

    const float* src; __half* dst;
    int mul, add;
    size_t bi, bo;
    // all jobs here: R=D_DIM rows, C=H_DIM cols
    if (z < 16)       { int e = z;      src = wg;  dst = wguT;  mul = 2; add = 0; bi = (size_t)e * D_DIM * H_DIM; bo = bi * 2; }
    else if (z < 32)  { int e = z - 16; src = wu;  dst = wguT;  mul = 2; add = 1; bi = (size_t)e * D_DIM * H_DIM; bo = bi * 2; }
    else if (z == 32) { src = swg; dst = swguT; mul = 2; add = 0; bi = 0; bo = 0; }
    else              { src = swu; dst = swguT; mul = 2; add = 1; bi = 0; bo = 0; }

    const int c0 = ct * 32, r0 = rt * 64;
    if (c0 >= H_DIM || r0 >= D_DIM) return;

    __shared__ float tile[32 * 65];
    tile_transpose(src, dst, D_DIM, H_DIM, mul, add, bi, bo, c0, r0, tile, t);
}

// scatter with in-block prefix over g_cnt
__global__ void scatter_kernel() {
    __shared__ int soff[E_NUM];
    int t = threadIdx.x;
    if (t == 0) {
        int a = 0;
        for (int e = 0; e < E_NUM; e++) { soff[e] = a; a += g_cnt[e]; }
    }
    __syncthreads();
    int id = blockIdx.x * 256 + t;
    if (id < NK) {
        int e = g_idx[id];
        int p = soff[e] + atomicAdd(&g_pos[e], 1);
        g_tok[p] = id / KSEL;
        g_tw[p]  = g_w[id];
        g_pmap[id] = p;
    }
}

// ---------------------------------------------------------------------------
// fp16 mma.sync GEMM (R10 best geometry): block 128x128, BK=64,
// warp grid 2(m)x4(n), m16n8k16, 3-stage cp.async, 2 CTAs/SM,
// ks-level fragment ping-pong. z<16 routed expert z, z==16 shared.
// GU only: z==17 = w_down/sw_down transpose slice (hidden under the GEMM;
// stream order makes it complete before the DN launch needs wdT).
// ---------------------------------------------------------------------------
#define ROWB    144
#define TILE_HB (128 * ROWB)
#define NSTG    3
#define SMEM_BYTES (2 * NSTG * TILE_HB + 1024)

template <bool GU>
__global__ void __launch_bounds__(256)
mma_gemm(const __half* __restrict__ Art, const __half* __restrict__ Ash,
         const __half* __restrict__ Brt, const __half* __restrict__ Bsh,
         __half* __restrict__ outRt, void* __restrict__ outShv,
         const float* __restrict__ wdsrc, const float* __restrict__ swdsrc,
         __half* __restrict__ wdTd, __half* __restrict__ swdTd) {
    constexpr int KD = GU ? D_DIM : H_DIM;
    const int e = blockIdx.z;
    const int t = threadIdx.x;

    extern __shared__ char smc[];

    if (GU && e == E_NUM + 1) {
        // ---- w_down / sw_down transpose-convert (R=H_DIM, C=D_DIM, mul=1) ----
        float* tile = (float*)smc;
        const int base = (blockIdx.y * 32 + blockIdx.x) * 17;   // 256 blocks x 17 jobs
#pragma unroll 1
        for (int j = 0; j < 17; j++) {
            const int job = base + j;                            // 0..4351
            const float* src; __half* dst;
            size_t bi;
            int rem;
            if (job < 4096) { int ex = job >> 8; rem = job & 255; src = wdsrc; dst = wdTd;
                              bi = (size_t)ex * H_DIM * D_DIM; }
            else            { rem = job - 4096; src = swdsrc; dst = swdTd; bi = 0; }
            const int c0 = (rem & 31) * 32;        // 32 c-tiles over C=1024
            const int r0 = (rem >> 5) * 64;        // 8 r-tiles over R=512
            tile_transpose(src, dst, H_DIM, D_DIM, 1, 0, bi, bi, c0, r0, tile, t);
        }
        return;
    }

    const bool gather = (e < E_NUM);
    const int cnt = gather ? g_cnt[e] : NTOK;
    const int m0  = blockIdx.x * 128;
    if (m0 >= cnt) return;
    int offr = 0;
    if (gather) {
        for (int q = 0; q < E_NUM; q++) offr += (q < e) ? g_cnt[q] : 0;
    }
    const int n0 = blockIdx.y * 128;

    const __half* A = gather ? Art : Ash;
    const __half* B = gather ? (Brt + (size_t)e * 1024 * KD) : Bsh;

    const uint32_t uA = smem_u32(smc);
    const uint32_t uB = uA + NSTG * TILE_HB;
    int*   rtok = (int*)(smc + 2 * NSTG * TILE_HB);
    float* twsh = (float*)(smc + 2 * NSTG * TILE_HB + 512);

    const int warp = t >> 5, lane = t & 31;
    const int wm = warp >> 2, wn = warp & 3;

    if (t < 128) {
        int gm = m0 + t;
        int cg = (gm < cnt) ? gm : 0;
        int src;
        if (GU) src = gather ? g_tok[offr + cg] : gm;
        else    src = gather ? (offr + gm) : gm;
        rtok[t] = src;
        twsh[t] = (GU && gather) ? g_tw[offr + cg] : 1.0f;
    }
    __syncthreads();

    const __half* aP[4];
    const __half* bP[4];
    uint32_t sOff[4];
#pragma unroll
    for (int j = 0; j < 4; j++) {
        int cidx = t + j * 256;
        int row = cidx >> 3, kc = cidx & 7;
        aP[j] = A + (size_t)rtok[row] * KD + kc * 8;
        bP[j] = B + (size_t)(n0 + row) * KD + kc * 8;
        sOff[j] = (uint32_t)(row * ROWB + kc * 16);
    }

    // ks-invariant ldsm address parts
    const uint32_t aRow = wm * 64 + (lane & 7) + ((lane >> 3) & 1) * 8;
    const uint32_t aCol = (lane >> 4) * 16;
    const uint32_t bRow0 = wn * 32 + ((lane >> 4) & 1) * 8 + (lane & 7);
    const uint32_t bCol = ((lane >> 3) & 1) * 16;

#define LOADSTAGE(s, k0) do {                                       \
        _Pragma("unroll")                                           \
        for (int j = 0; j < 4; j++) {                               \
            cp16(uA + (s) * TILE_HB + sOff[j], aP[j] + (k0));       \
            cp16(uB + (s) * TILE_HB + sOff[j], bP[j] + (k0));       \
        }                                                           \
    } while (0)

#define LOADFRAG(q, uAs, uBs, ks) do {                                            \
        _Pragma("unroll")                                                         \
        for (int mt = 0; mt < 4; mt++) {                                          \
            uint32_t ad = (uAs) + (aRow + mt * 16) * ROWB + (ks) * 32 + aCol;     \
            ldm4(afr[q][mt][0], afr[q][mt][1], afr[q][mt][2], afr[q][mt][3], ad); \
        }                                                                         \
        _Pragma("unroll")                                                         \
        for (int p = 0; p < 2; p++) {                                             \
            uint32_t ad = (uBs) + (bRow0 + p * 16) * ROWB + (ks) * 32 + bCol;     \
            ldm4(bfr[q][p][0], bfr[q][p][1], bfr[q][p][2], bfr[q][p][3], ad);     \
        }                                                                         \
    } while (0)

    float c[4][4][4] = {};
    uint32_t afr[2][4][4], bfr[2][2][4];

    const int NIT = KD / 64;
    LOADSTAGE(0, 0);  CP_COMMIT();
    LOADSTAGE(1, 64); CP_COMMIT();

    for (int i = 0; i < NIT; i++) {
        CP_WAIT1();
        __syncthreads();
        const int ld = i + 2;
        if (ld < NIT) LOADSTAGE(ld % NSTG, ld * 64);
        CP_COMMIT();

        const int s = i % NSTG;
        const uint32_t uAs = uA + s * TILE_HB;
        const uint32_t uBs = uB + s * TILE_HB;

        LOADFRAG(0, uAs, uBs, 0);
#pragma unroll
        for (int ks = 0; ks < 4; ks++) {
            const int cur = ks & 1;
            if (ks < 3) LOADFRAG(cur ^ 1, uAs, uBs, ks + 1);
#pragma unroll
            for (int mt = 0; mt < 4; mt++) {
#pragma unroll
                for (int nt = 0; nt < 4; nt++)
                    mma16(c[mt][nt], afr[cur][mt],
                          bfr[cur][nt >> 1][2 * (nt & 1)], bfr[cur][nt >> 1][2 * (nt & 1) + 1]);
            }
        }
    }
#undef LOADSTAGE
#undef LOADFRAG

#pragma unroll
    for (int mt = 0; mt < 4; mt++) {
        int r0 = wm * 64 + mt * 16 + (lane >> 2);
#pragma unroll
        for (int pass = 0; pass < 2; pass++) {
            int r = r0 + pass * 8;
            int gm = m0 + r;
            if (gm < cnt) {
                if (GU) {
                    float tw = twsh[r];
                    __half* orow = (gather ? outRt + (size_t)(offr + gm) * H_DIM
                                           : (__half*)outShv + (size_t)gm * H_DIM);
#pragma unroll
                    for (int nt = 0; nt < 4; nt++) {
                        float g = c[mt][nt][pass * 2];
                        float u = c[mt][nt][pass * 2 + 1];
                        int h = (n0 + wn * 32 + nt * 8) / 2 + (lane & 3);
                        orow[h] = __float2half_rn(tw * u * g / (1.0f + __expf(-g)));
                    }
                } else if (gather) {
                    __half* orow = outRt + (size_t)(offr + gm) * D_DIM;
#pragma unroll
                    for (int nt = 0; nt < 4; nt++) {
                        int n = n0 + wn * 32 + nt * 8 + 2 * (lane & 3);
                        *(__half2*)(orow + n) =
                            __floats2half2_rn(c[mt][nt][pass * 2], c[mt][nt][pass * 2 + 1]);
                    }
                } else {
                    float* orow = (float*)outShv + (size_t)gm * D_DIM;
#pragma unroll
                    for (int nt = 0; nt < 4; nt++) {
                        int n = n0 + wn * 32 + nt * 8 + 2 * (lane & 3);
                        *(float2*)(orow + n) =
                            make_float2(c[mt][nt][pass * 2], c[mt][nt][pass * 2 + 1]);
                    }
                }
            }
        }
    }
}

// ---------------------------------------------------------------------------
// combine: out[n] (shared result) += sum_k g_yh[pmap[n,k]]  (fp16 reads)
// ---------------------------------------------------------------------------
__global__ void combine_kernel(float* __restrict__ out) {
    const int n = blockIdx.x, t = threadIdx.x;
    __shared__ int pm[KSEL];
    if (t < KSEL) pm[t] = g_pmap[n * KSEL + t];
    __syncthreads();
    float4 acc = *(const float4*)(out + (size_t)n * D_DIM + t * 4);
#pragma unroll
    for (int k = 0; k < KSEL; k++) {
        const __half2* p = (const __half2*)(g_yh + (size_t)pm[k] * D_DIM + t * 4);
        float2 v0 = __half22float2(p[0]);
        float2 v1 = __half22float2(p[1]);
        acc.x += v0.x; acc.y += v0.y; acc.z += v1.x; acc.w += v1.y;
    }
    *(float4*)(out + (size_t)n * D_DIM + t * 4) = acc;
}

// ---------------------------------------------------------------------------
// Launch:  gwnorm(1) fused_pg(2) scatter(3) GU(4, incl wd-prep z=17) DN(5) combine(6)
// ---------------------------------------------------------------------------
extern "C" void kernel_launch(void* const* d_in, const int* in_sizes, int n_in,
                              void* d_out, int out_size) {
    (void)in_sizes; (void)n_in; (void)out_size;
    const float* x       = (const float*)d_in[0];
    const float* gate_w  = (const float*)d_in[1];
    const float* w_gate  = (const float*)d_in[2];
    const float* w_up    = (const float*)d_in[3];
    const float* w_down  = (const float*)d_in[4];
    const float* sw_gate = (const float*)d_in[5];
    const float* sw_up   = (const float*)d_in[6];
    const float* sw_down = (const float*)d_in[7];
    float* out = (float*)d_out;

    cudaFuncSetAttribute(mma_gemm<true>,  cudaFuncAttributeMaxDynamicSharedMemorySize, SMEM_BYTES);
    cudaFuncSetAttribute(mma_gemm<false>, cudaFuncAttributeMaxDynamicSharedMemorySize, SMEM_BYTES);

    __half* xt; __half* wguT; __half* wdT; __half* swguT; __half* swdT;
    __half* hbuf; __half* hsbuf; __half* ybuf;
    cudaGetSymbolAddress((void**)&xt,    g_xt);
    cudaGetSymbolAddress((void**)&wguT,  g_wguT);
    cudaGetSymbolAddress((void**)&wdT,   g_wdT);
    cudaGetSymbolAddress((void**)&swguT, g_swguT);
    cudaGetSymbolAddress((void**)&swdT,  g_swdT);
    cudaGetSymbolAddress((void**)&hbuf,  g_h);
    cudaGetSymbolAddress((void**)&hsbuf, g_hs);
    cudaGetSymbolAddress((void**)&ybuf,  g_yh);

    gwnorm_kernel<<<E_NUM, 256>>>(gate_w);

    // gating (4096 blocks) + gate/up transposes (34 x 512 blocks)
    fused_pg_kernel<<<NTOK + 34 * 512, 256>>>(
        x, w_gate, w_up, sw_gate, sw_up, wguT, swguT);

    scatter_kernel<<<(NK + 255) / 256, 256>>>();

    // GU: routed (z<16) + shared (z==16) + w_down prep slice (z==17)
    mma_gemm<true><<<dim3(32, 8, E_NUM + 2), 256, SMEM_BYTES>>>(
        xt, xt, wguT, swguT, hbuf, (void*)hsbuf, w_down, sw_down, wdT, swdT);

    // DN: routed -> g_yh (fp16), shared -> out (fp32)
    mma_gemm<false><<<dim3(32, 8, E_NUM + 1), 256, SMEM_BYTES>>>(
        hbuf, hsbuf, wdT, swdT, ybuf, (void*)out, nullptr, nullptr, nullptr, nullptr);

    combine_kernel<<<NTOK, 256>>>(out);
}

// round 15
// speedup vs baseline: 1.1860x; 1.0091x over previous
#include <cuda_runtime.h>
#include <cuda_fp16.h>
#include <cstdint>
#include <math.h>

#define D_DIM 1024
#define H_DIM 512
#define E_NUM 16
#define NTOK  4096
#define KSEL  8
#define NK    (NTOK * KSEL)

// ---------------------------------------------------------------------------
// Device scratch
// ---------------------------------------------------------------------------
__device__ float g_gwn[E_NUM * D_DIM];
__device__ int   g_idx[NK];
__device__ float g_w[NK];
__device__ int   g_cnt[E_NUM];
__device__ int   g_pos[E_NUM];
__device__ int   g_tok[NK + 128];
__device__ float g_tw[NK + 128];
__device__ int   g_pmap[NK];

__device__ __half g_xt[(size_t)NTOK * D_DIM];                // fp16 x
__device__ __half g_wguT[(size_t)E_NUM * 2 * H_DIM * D_DIM]; // [E][2H][D] interleaved gate/up
__device__ __half g_wdT [(size_t)E_NUM * D_DIM * H_DIM];     // [E][D][H]
__device__ __half g_swguT[(size_t)2 * H_DIM * D_DIM];
__device__ __half g_swdT [(size_t)D_DIM * H_DIM];

__device__ __half g_h [((size_t)NK + 128) * H_DIM];          // routed hidden (weighted)
__device__ __half g_hs[(size_t)NTOK * H_DIM];                // shared hidden
__device__ __half g_yh[(size_t)NK * D_DIM];                  // routed down output (fp16)

// ---------------------------------------------------------------------------
// Helpers (sm_80-compatible PTX only — harness compiles for plain sm_100)
// ---------------------------------------------------------------------------
__device__ __forceinline__ uint32_t smem_u32(const void* p) {
    uint32_t a;
    asm("{ .reg .u64 t; cvta.to.shared.u64 t, %1; cvt.u32.u64 %0, t; }" : "=r"(a) : "l"(p));
    return a;
}
__device__ __forceinline__ void cp16(uint32_t dst, const void* src) {
    asm volatile("cp.async.cg.shared.global [%0], [%1], 16;" :: "r"(dst), "l"(src));
}
#define CP_COMMIT() asm volatile("cp.async.commit_group;" ::: "memory")
#define CP_WAIT2()  asm volatile("cp.async.wait_group 2;" ::: "memory")
#define CP_WAIT0()  asm volatile("cp.async.wait_group 0;" ::: "memory")

__device__ __forceinline__ void ldm4(uint32_t& r0, uint32_t& r1, uint32_t& r2, uint32_t& r3,
                                     uint32_t a) {
    asm volatile("ldmatrix.sync.aligned.m8n8.x4.shared.b16 {%0,%1,%2,%3}, [%4];"
                 : "=r"(r0), "=r"(r1), "=r"(r2), "=r"(r3) : "r"(a));
}
__device__ __forceinline__ void mma16(float* c, const uint32_t* a, uint32_t b0, uint32_t b1) {
    asm volatile("mma.sync.aligned.m16n8k16.row.col.f32.f16.f16.f32 "
                 "{%0,%1,%2,%3}, {%4,%5,%6,%7}, {%8,%9}, {%0,%1,%2,%3};"
                 : "+f"(c[0]), "+f"(c[1]), "+f"(c[2]), "+f"(c[3])
                 : "r"(a[0]), "r"(a[1]), "r"(a[2]), "r"(a[3]), "r"(b0), "r"(b1));
}

// shared 64r x 32c transpose-convert tile step (smem provided by caller)
__device__ __forceinline__ void tile_transpose(const float* src, __half* dst,
                                               int R, int C, int mul, int add,
                                               size_t bi, size_t bo,
                                               int c0, int r0, float* tile, int t) {
    const int tx = t & 31, ty = t >> 5;   // 32 x 8
#pragma unroll
    for (int j = 0; j < 64; j += 8)
        tile[tx * 65 + ty + j] = src[bi + (size_t)(r0 + ty + j) * C + c0 + tx];
    __syncthreads();
#pragma unroll
    for (int jc = 0; jc < 4; jc++) {
        int c = ty + jc * 8;
        __half2 v = __floats2half2_rn(tile[c * 65 + 2 * tx], tile[c * 65 + 2 * tx + 1]);
        *(__half2*)(dst + bo + (size_t)((c0 + c) * mul + add) * R + r0 + 2 * tx) = v;
    }
    __syncthreads();
}

// ---------------------------------------------------------------------------
// gwnorm: must precede gating. Also zeroes counters.
// ---------------------------------------------------------------------------
__global__ void gwnorm_kernel(const float* __restrict__ gw) {
    int e = blockIdx.x, t = threadIdx.x;
    if (e == 0 && t < E_NUM) { g_cnt[t] = 0; g_pos[t] = 0; }
    __shared__ float red[8];
    float ss = 0.f;
    for (int i = t; i < D_DIM; i += 256) { float v = gw[e * D_DIM + i]; ss += v * v; }
    for (int o = 16; o; o >>= 1) ss += __shfl_down_sync(0xFFFFFFFFu, ss, o);
    if ((t & 31) == 0) red[t >> 5] = ss;
    __syncthreads();
    __shared__ float s_inv;
    if (t == 0) {
        float tot = 0.f;
        for (int i = 0; i < 8; i++) tot += red[i];
        s_inv = 1.0f / fmaxf(sqrtf(tot), 1e-12f);
    }
    __syncthreads();
    float inv = s_inv;
    for (int i = t; i < D_DIM; i += 256) g_gwn[e * D_DIM + i] = gw[e * D_DIM + i] * inv;
}

// ---------------------------------------------------------------------------
// fused gating + GU-weight prep (wg/wu/swg/swu; wd lives in the GU launch).
// ---------------------------------------------------------------------------
__global__ void fused_pg_kernel(const float* __restrict__ x,
                                const float* __restrict__ wg, const float* __restrict__ wu,
                                const float* __restrict__ swg, const float* __restrict__ swu,
                                __half* __restrict__ wguT, __half* __restrict__ swguT) {
    const int bid = blockIdx.x;
    const int t = threadIdx.x;

    if (bid < NTOK) {
        const int n = bid;
        const int warp = t >> 5, lane = t & 31;
        __shared__ float sx[D_DIM];
        __shared__ float red[8];
        __shared__ float slog[E_NUM];
        const float* xr = x + (size_t)n * D_DIM;
        // one float4 per thread covers the whole row
        float4 v4 = ((const float4*)xr)[t];
        ((float4*)sx)[t] = v4;
        float ss = v4.x * v4.x + v4.y * v4.y + v4.z * v4.z + v4.w * v4.w;
        for (int o = 16; o; o >>= 1) ss += __shfl_down_sync(0xFFFFFFFFu, ss, o);
        if (lane == 0) red[warp] = ss;
        __syncthreads();
        // fp16 copy out (2 x half2 per thread = 16B aligned store)
        {
            __half2 h0 = __floats2half2_rn(v4.x, v4.y);
            __half2 h1 = __floats2half2_rn(v4.z, v4.w);
            __half2* xo = (__half2*)(g_xt + (size_t)n * D_DIM) + 2 * t;
            xo[0] = h0;
            xo[1] = h1;
        }
        for (int j = 0; j < 2; j++) {
            int e = warp * 2 + j;
            const float* g = g_gwn + e * D_DIM;
            float d = 0.f;
            for (int i = lane; i < D_DIM; i += 32) d += sx[i] * g[i];
            for (int o = 16; o; o >>= 1) d += __shfl_down_sync(0xFFFFFFFFu, d, o);
            if (lane == 0) slog[e] = d;
        }
        __syncthreads();
        if (t == 0) {
            float ssq = 0.f;
            for (int i = 0; i < 8; i++) ssq += red[i];
            float inv = 1.0f / fmaxf(sqrtf(ssq), 1e-12f);
            float sc[E_NUM];
            for (int e = 0; e < E_NUM; e++) sc[e] = slog[e] * inv;
            int sel[KSEL]; float sw[KSEL]; float wsum = 0.f;
            for (int k = 0; k < KSEL; k++) {
                int bi = 0; float bv = -1e30f;
                for (int e = 0; e < E_NUM; e++)
                    if (sc[e] > bv) { bv = sc[e]; bi = e; }
                sel[k] = bi;
                float s = 1.0f / (1.0f + __expf(-bv));
                sw[k] = s; wsum += s; sc[bi] = -1e30f;
            }
            float invw = 1.0f / wsum;
            for (int k = 0; k < KSEL; k++) {
                g_idx[n * KSEL + k] = sel[k];
                g_w[n * KSEL + k]   = sw[k] * invw;
                atomicAdd(&g_cnt[sel[k]], 1);
            }
        }
        return;
    }

    const int p = bid - NTOK;
    const int z = p >> 9;
    const int ct = p & 31;
    const int rt = (p >> 5) & 15;

    const float* src; __half* dst;
    int mul, add;
    size_t bi, bo;
    if (z < 16)       { int e = z;      src = wg;  dst = wguT;  mul = 2; add = 0; bi = (size_t)e * D_DIM * H_DIM; bo = bi * 2; }
    else if (z < 32)  { int e = z - 16; src = wu;  dst = wguT;  mul = 2; add = 1; bi = (size_t)e * D_DIM * H_DIM; bo = bi * 2; }
    else if (z == 32) { src = swg; dst = swguT; mul = 2; add = 0; bi = 0; bo = 0; }
    else              { src = swu; dst = swguT; mul = 2; add = 1; bi = 0; bo = 0; }

    const int c0 = ct * 32, r0 = rt * 64;
    if (c0 >= H_DIM || r0 >= D_DIM) return;

    __shared__ float tile[32 * 65];
    tile_transpose(src, dst, D_DIM, H_DIM, mul, add, bi, bo, c0, r0, tile, t);
}

// scatter with in-block prefix over g_cnt
__global__ void scatter_kernel() {
    __shared__ int soff[E_NUM];
    int t = threadIdx.x;
    if (t == 0) {
        int a = 0;
        for (int e = 0; e < E_NUM; e++) { soff[e] = a; a += g_cnt[e]; }
    }
    __syncthreads();
    int id = blockIdx.x * 256 + t;
    if (id < NK) {
        int e = g_idx[id];
        int p = soff[e] + atomicAdd(&g_pos[e], 1);
        g_tok[p] = id / KSEL;
        g_tw[p]  = g_w[id];
        g_pmap[id] = p;
    }
}

// ---------------------------------------------------------------------------
// fp16 mma.sync GEMM (best geometry): block 128x128, BK=64, warp grid 2x4,
// m16n8k16, 3-stage cp.async with MAX slack (load i+2 issued BEFORE waiting),
// ks-level fragment ping-pong, 2 CTAs/SM. z<16 routed, z==16 shared.
// GU only: z==17 = w_down/sw_down transpose slice.
// ---------------------------------------------------------------------------
#define ROWB    144
#define TILE_HB (128 * ROWB)
#define NSTG    3
#define SMEM_BYTES (2 * NSTG * TILE_HB + 1024)

template <bool GU>
__global__ void __launch_bounds__(256)
mma_gemm(const __half* __restrict__ Art, const __half* __restrict__ Ash,
         const __half* __restrict__ Brt, const __half* __restrict__ Bsh,
         __half* __restrict__ outRt, void* __restrict__ outShv,
         const float* __restrict__ wdsrc, const float* __restrict__ swdsrc,
         __half* __restrict__ wdTd, __half* __restrict__ swdTd) {
    constexpr int KD = GU ? D_DIM : H_DIM;
    const int e = blockIdx.z;
    const int t = threadIdx.x;

    extern __shared__ char smc[];

    if (GU && e == E_NUM + 1) {
        float* tile = (float*)smc;
        const int base = (blockIdx.y * 32 + blockIdx.x) * 17;
#pragma unroll 1
        for (int j = 0; j < 17; j++) {
            const int job = base + j;
            const float* src; __half* dst;
            size_t bi;
            int rem;
            if (job < 4096) { int ex = job >> 8; rem = job & 255; src = wdsrc; dst = wdTd;
                              bi = (size_t)ex * H_DIM * D_DIM; }
            else            { rem = job - 4096; src = swdsrc; dst = swdTd; bi = 0; }
            const int c0 = (rem & 31) * 32;
            const int r0 = (rem >> 5) * 64;
            tile_transpose(src, dst, H_DIM, D_DIM, 1, 0, bi, bi, c0, r0, tile, t);
        }
        return;
    }

    const bool gather = (e < E_NUM);
    const int cnt = gather ? g_cnt[e] : NTOK;
    const int m0  = blockIdx.x * 128;
    if (m0 >= cnt) return;
    int offr = 0;
    if (gather) {
        for (int q = 0; q < E_NUM; q++) offr += (q < e) ? g_cnt[q] : 0;
    }
    const int n0 = blockIdx.y * 128;

    const __half* A = gather ? Art : Ash;
    const __half* B = gather ? (Brt + (size_t)e * 1024 * KD) : Bsh;

    const uint32_t uA = smem_u32(smc);
    const uint32_t uB = uA + NSTG * TILE_HB;
    int*   rtok = (int*)(smc + 2 * NSTG * TILE_HB);
    float* twsh = (float*)(smc + 2 * NSTG * TILE_HB + 512);

    const int warp = t >> 5, lane = t & 31;
    const int wm = warp >> 2, wn = warp & 3;

    if (t < 128) {
        int gm = m0 + t;
        int cg = (gm < cnt) ? gm : 0;
        int src;
        if (GU) src = gather ? g_tok[offr + cg] : gm;
        else    src = gather ? (offr + gm) : gm;
        rtok[t] = src;
        twsh[t] = (GU && gather) ? g_tw[offr + cg] : 1.0f;
    }
    __syncthreads();

    const __half* aP[4];
    const __half* bP[4];
    uint32_t sOff[4];
#pragma unroll
    for (int j = 0; j < 4; j++) {
        int cidx = t + j * 256;
        int row = cidx >> 3, kc = cidx & 7;
        aP[j] = A + (size_t)rtok[row] * KD + kc * 8;
        bP[j] = B + (size_t)(n0 + row) * KD + kc * 8;
        sOff[j] = (uint32_t)(row * ROWB + kc * 16);
    }

    const uint32_t aRow = wm * 64 + (lane & 7) + ((lane >> 3) & 1) * 8;
    const uint32_t aCol = (lane >> 4) * 16;
    const uint32_t bRow0 = wn * 32 + ((lane >> 4) & 1) * 8 + (lane & 7);
    const uint32_t bCol = ((lane >> 3) & 1) * 16;

#define LOADSTAGE(s, k0) do {                                       \
        _Pragma("unroll")                                           \
        for (int j = 0; j < 4; j++) {                               \
            cp16(uA + (s) * TILE_HB + sOff[j], aP[j] + (k0));       \
            cp16(uB + (s) * TILE_HB + sOff[j], bP[j] + (k0));       \
        }                                                           \
    } while (0)

#define LOADFRAG(q, uAs, uBs, ks) do {                                            \
        _Pragma("unroll")                                                         \
        for (int mt = 0; mt < 4; mt++) {                                          \
            uint32_t ad = (uAs) + (aRow + mt * 16) * ROWB + (ks) * 32 + aCol;     \
            ldm4(afr[q][mt][0], afr[q][mt][1], afr[q][mt][2], afr[q][mt][3], ad); \
        }                                                                         \
        _Pragma("unroll")                                                         \
        for (int p = 0; p < 2; p++) {                                             \
            uint32_t ad = (uBs) + (bRow0 + p * 16) * ROWB + (ks) * 32 + bCol;     \
            ldm4(bfr[q][p][0], bfr[q][p][1], bfr[q][p][2], bfr[q][p][3], ad);     \
        }                                                                         \
    } while (0)

    float c[4][4][4] = {};
    uint32_t afr[2][4][4], bfr[2][2][4];

    const int NIT = KD / 64;
    LOADSTAGE(0, 0);  CP_COMMIT();
    LOADSTAGE(1, 64); CP_COMMIT();

    for (int i = 0; i < NIT; i++) {
        // Issue chunk i+2's load BEFORE waiting: keeps 2 groups pending and
        // gives every load ~2 full compute phases of latency budget.
        // WAR safety: stage (i+2)%3 was last READ at chunk i-1, and all warps
        // finished chunk i-1 before the barrier at the PREVIOUS iteration; to
        // keep the same guarantee with the reordered issue we place the
        // barrier before the load via the loop-carried structure below.
        __syncthreads();                 // all warps done reading stage (i+2)%3 (chunk i-1)
        const int ld = i + 2;
        if (ld < NIT) { LOADSTAGE(ld % NSTG, ld * 64); }
        CP_COMMIT();
        CP_WAIT2();                      // need g_i (chunk i) complete; leaves i+1, i+2 pending
        __syncthreads();                 // publish stage i%3 data to all warps

        const int s = i % NSTG;
        const uint32_t uAs = uA + s * TILE_HB;
        const uint32_t uBs = uB + s * TILE_HB;

        LOADFRAG(0, uAs, uBs, 0);
#pragma unroll
        for (int ks = 0; ks < 4; ks++) {
            const int cur = ks & 1;
            if (ks < 3) LOADFRAG(cur ^ 1, uAs, uBs, ks + 1);
#pragma unroll
            for (int mt = 0; mt < 4; mt++) {
#pragma unroll
                for (int nt = 0; nt < 4; nt++)
                    mma16(c[mt][nt], afr[cur][mt],
                          bfr[cur][nt >> 1][2 * (nt & 1)], bfr[cur][nt >> 1][2 * (nt & 1) + 1]);
            }
        }
    }
#undef LOADSTAGE
#undef LOADFRAG

#pragma unroll
    for (int mt = 0; mt < 4; mt++) {
        int r0 = wm * 64 + mt * 16 + (lane >> 2);
#pragma unroll
        for (int pass = 0; pass < 2; pass++) {
            int r = r0 + pass * 8;
            int gm = m0 + r;
            if (gm < cnt) {
                if (GU) {
                    float tw = twsh[r];
                    __half* orow = (gather ? outRt + (size_t)(offr + gm) * H_DIM
                                           : (__half*)outShv + (size_t)gm * H_DIM);
#pragma unroll
                    for (int nt = 0; nt < 4; nt++) {
                        float g = c[mt][nt][pass * 2];
                        float u = c[mt][nt][pass * 2 + 1];
                        int h = (n0 + wn * 32 + nt * 8) / 2 + (lane & 3);
                        orow[h] = __float2half_rn(tw * u * g / (1.0f + __expf(-g)));
                    }
                } else if (gather) {
                    __half* orow = outRt + (size_t)(offr + gm) * D_DIM;
#pragma unroll
                    for (int nt = 0; nt < 4; nt++) {
                        int n = n0 + wn * 32 + nt * 8 + 2 * (lane & 3);
                        *(__half2*)(orow + n) =
                            __floats2half2_rn(c[mt][nt][pass * 2], c[mt][nt][pass * 2 + 1]);
                    }
                } else {
                    float* orow = (float*)outShv + (size_t)gm * D_DIM;
#pragma unroll
                    for (int nt = 0; nt < 4; nt++) {
                        int n = n0 + wn * 32 + nt * 8 + 2 * (lane & 3);
                        *(float2*)(orow + n) =
                            make_float2(c[mt][nt][pass * 2], c[mt][nt][pass * 2 + 1]);
                    }
                }
            }
        }
    }
}

// ---------------------------------------------------------------------------
// combine: out[n] (shared result) += sum_k g_yh[pmap[n,k]]  (fp16 reads)
// ---------------------------------------------------------------------------
__global__ void combine_kernel(float* __restrict__ out) {
    const int n = blockIdx.x, t = threadIdx.x;
    __shared__ int pm[KSEL];
    if (t < KSEL) pm[t] = g_pmap[n * KSEL + t];
    __syncthreads();
    float4 acc = *(const float4*)(out + (size_t)n * D_DIM + t * 4);
#pragma unroll
    for (int k = 0; k < KSEL; k++) {
        const __half2* p = (const __half2*)(g_yh + (size_t)pm[k] * D_DIM + t * 4);
        float2 v0 = __half22float2(p[0]);
        float2 v1 = __half22float2(p[1]);
        acc.x += v0.x; acc.y += v0.y; acc.z += v1.x; acc.w += v1.y;
    }
    *(float4*)(out + (size_t)n * D_DIM + t * 4) = acc;
}

// ---------------------------------------------------------------------------
// Launch:  gwnorm(1) fused_pg(2) scatter(3) GU(4, incl wd-prep) DN(5) combine(6)
// ---------------------------------------------------------------------------
extern "C" void kernel_launch(void* const* d_in, const int* in_sizes, int n_in,
                              void* d_out, int out_size) {
    (void)in_sizes; (void)n_in; (void)out_size;
    const float* x       = (const float*)d_in[0];
    const float* gate_w  = (const float*)d_in[1];
    const float* w_gate  = (const float*)d_in[2];
    const float* w_up    = (const float*)d_in[3];
    const float* w_down  = (const float*)d_in[4];
    const float* sw_gate = (const float*)d_in[5];
    const float* sw_up   = (const float*)d_in[6];
    const float* sw_down = (const float*)d_in[7];
    float* out = (float*)d_out;

    cudaFuncSetAttribute(mma_gemm<true>,  cudaFuncAttributeMaxDynamicSharedMemorySize, SMEM_BYTES);
    cudaFuncSetAttribute(mma_gemm<false>, cudaFuncAttributeMaxDynamicSharedMemorySize, SMEM_BYTES);

    __half* xt; __half* wguT; __half* wdT; __half* swguT; __half* swdT;
    __half* hbuf; __half* hsbuf; __half* ybuf;
    cudaGetSymbolAddress((void**)&xt,    g_xt);
    cudaGetSymbolAddress((void**)&wguT,  g_wguT);
    cudaGetSymbolAddress((void**)&wdT,   g_wdT);
    cudaGetSymbolAddress((void**)&swguT, g_swguT);
    cudaGetSymbolAddress((void**)&swdT,  g_swdT);
    cudaGetSymbolAddress((void**)&hbuf,  g_h);
    cudaGetSymbolAddress((void**)&hsbuf, g_hs);
    cudaGetSymbolAddress((void**)&ybuf,  g_yh);

    gwnorm_kernel<<<E_NUM, 256>>>(gate_w);

    fused_pg_kernel<<<NTOK + 34 * 512, 256>>>(
        x, w_gate, w_up, sw_gate, sw_up, wguT, swguT);

    scatter_kernel<<<(NK + 255) / 256, 256>>>();

    // GU: routed (z<16) + shared (z==16) + w_down prep slice (z==17)
    mma_gemm<true><<<dim3(32, 8, E_NUM + 2), 256, SMEM_BYTES>>>(
        xt, xt, wguT, swguT, hbuf, (void*)hsbuf, w_down, sw_down, wdT, swdT);

    // DN: routed -> g_yh (fp16), shared -> out (fp32)
    mma_gemm<false><<<dim3(32, 8, E_NUM + 1), 256, SMEM_BYTES>>>(
        hbuf, hsbuf, wdT, swdT, ybuf, (void*)out, nullptr, nullptr, nullptr, nullptr);

    combine_kernel<<<NTOK, 256>>>(out);
}

// round 16
// speedup vs baseline: 1.1869x; 1.0008x over previous
#include <cuda_runtime.h>
#include <cuda_fp16.h>
#include <cstdint>
#include <math.h>

#define D_DIM 1024
#define H_DIM 512
#define E_NUM 16
#define NTOK  4096
#define KSEL  8
#define NK    (NTOK * KSEL)

// ---------------------------------------------------------------------------
// Device scratch
// ---------------------------------------------------------------------------
__device__ float g_gwn[E_NUM * D_DIM];
__device__ int   g_idx[NK];
__device__ float g_w[NK];
__device__ int   g_cnt[E_NUM];
__device__ int   g_pos[E_NUM];
__device__ int   g_tok[NK + 128];
__device__ float g_tw[NK + 128];
__device__ int   g_pmap[NK];

__device__ __half g_xt[(size_t)NTOK * D_DIM];                // fp16 x
__device__ __half g_wguT[(size_t)E_NUM * 2 * H_DIM * D_DIM]; // [E][2H][D] interleaved gate/up
__device__ __half g_wdT [(size_t)E_NUM * D_DIM * H_DIM];     // [E][D][H]
__device__ __half g_swguT[(size_t)2 * H_DIM * D_DIM];
__device__ __half g_swdT [(size_t)D_DIM * H_DIM];

__device__ __half g_h [((size_t)NK + 128) * H_DIM];          // routed hidden (weighted)
__device__ __half g_hs[(size_t)NTOK * H_DIM];                // shared hidden
__device__ __half g_yh[(size_t)NK * D_DIM];                  // routed down output (fp16)
__device__ __half g_ysh[(size_t)NTOK * D_DIM];               // shared down output (fp16)

// ---------------------------------------------------------------------------
// Helpers (sm_80-compatible PTX only — harness compiles for plain sm_100)
// ---------------------------------------------------------------------------
__device__ __forceinline__ uint32_t smem_u32(const void* p) {
    uint32_t a;
    asm("{ .reg .u64 t; cvta.to.shared.u64 t, %1; cvt.u32.u64 %0, t; }" : "=r"(a) : "l"(p));
    return a;
}
__device__ __forceinline__ void cp16(uint32_t dst, const void* src) {
    asm volatile("cp.async.cg.shared.global [%0], [%1], 16;" :: "r"(dst), "l"(src));
}
#define CP_COMMIT() asm volatile("cp.async.commit_group;" ::: "memory")
#define CP_WAIT2()  asm volatile("cp.async.wait_group 2;" ::: "memory")

__device__ __forceinline__ void ldm4(uint32_t& r0, uint32_t& r1, uint32_t& r2, uint32_t& r3,
                                     uint32_t a) {
    asm volatile("ldmatrix.sync.aligned.m8n8.x4.shared.b16 {%0,%1,%2,%3}, [%4];"
                 : "=r"(r0), "=r"(r1), "=r"(r2), "=r"(r3) : "r"(a));
}
__device__ __forceinline__ void mma16(float* c, const uint32_t* a, uint32_t b0, uint32_t b1) {
    asm volatile("mma.sync.aligned.m16n8k16.row.col.f32.f16.f16.f32 "
                 "{%0,%1,%2,%3}, {%4,%5,%6,%7}, {%8,%9}, {%0,%1,%2,%3};"
                 : "+f"(c[0]), "+f"(c[1]), "+f"(c[2]), "+f"(c[3])
                 : "r"(a[0]), "r"(a[1]), "r"(a[2]), "r"(a[3]), "r"(b0), "r"(b1));
}

// shared 64r x 32c transpose-convert tile step (smem provided by caller)
__device__ __forceinline__ void tile_transpose(const float* src, __half* dst,
                                               int R, int C, int mul, int add,
                                               size_t bi, size_t bo,
                                               int c0, int r0, float* tile, int t) {
    const int tx = t & 31, ty = t >> 5;   // 32 x 8
#pragma unroll
    for (int j = 0; j < 64; j += 8)
        tile[tx * 65 + ty + j] = src[bi + (size_t)(r0 + ty + j) * C + c0 + tx];
    __syncthreads();
#pragma unroll
    for (int jc = 0; jc < 4; jc++) {
        int c = ty + jc * 8;
        __half2 v = __floats2half2_rn(tile[c * 65 + 2 * tx], tile[c * 65 + 2 * tx + 1]);
        *(__half2*)(dst + bo + (size_t)((c0 + c) * mul + add) * R + r0 + 2 * tx) = v;
    }
    __syncthreads();
}

// ---------------------------------------------------------------------------
// gwnorm: must precede gating. Also zeroes counters.
// ---------------------------------------------------------------------------
__global__ void gwnorm_kernel(const float* __restrict__ gw) {
    int e = blockIdx.x, t = threadIdx.x;
    if (e == 0 && t < E_NUM) { g_cnt[t] = 0; g_pos[t] = 0; }
    __shared__ float red[8];
    float ss = 0.f;
    for (int i = t; i < D_DIM; i += 256) { float v = gw[e * D_DIM + i]; ss += v * v; }
    for (int o = 16; o; o >>= 1) ss += __shfl_down_sync(0xFFFFFFFFu, ss, o);
    if ((t & 31) == 0) red[t >> 5] = ss;
    __syncthreads();
    __shared__ float s_inv;
    if (t == 0) {
        float tot = 0.f;
        for (int i = 0; i < 8; i++) tot += red[i];
        s_inv = 1.0f / fmaxf(sqrtf(tot), 1e-12f);
    }
    __syncthreads();
    float inv = s_inv;
    for (int i = t; i < D_DIM; i += 256) g_gwn[e * D_DIM + i] = gw[e * D_DIM + i] * inv;
}

// ---------------------------------------------------------------------------
// fused gating + GU-weight prep (wg/wu/swg/swu; wd lives in the GU launch).
// ---------------------------------------------------------------------------
__global__ void fused_pg_kernel(const float* __restrict__ x,
                                const float* __restrict__ wg, const float* __restrict__ wu,
                                const float* __restrict__ swg, const float* __restrict__ swu,
                                __half* __restrict__ wguT, __half* __restrict__ swguT) {
    const int bid = blockIdx.x;
    const int t = threadIdx.x;

    if (bid < NTOK) {
        const int n = bid;
        const int warp = t >> 5, lane = t & 31;
        __shared__ float sx[D_DIM];
        __shared__ float red[8];
        __shared__ float slog[E_NUM];
        const float* xr = x + (size_t)n * D_DIM;
        float4 v4 = ((const float4*)xr)[t];
        ((float4*)sx)[t] = v4;
        float ss = v4.x * v4.x + v4.y * v4.y + v4.z * v4.z + v4.w * v4.w;
        for (int o = 16; o; o >>= 1) ss += __shfl_down_sync(0xFFFFFFFFu, ss, o);
        if (lane == 0) red[warp] = ss;
        __syncthreads();
        {
            __half2 h0 = __floats2half2_rn(v4.x, v4.y);
            __half2 h1 = __floats2half2_rn(v4.z, v4.w);
            __half2* xo = (__half2*)(g_xt + (size_t)n * D_DIM) + 2 * t;
            xo[0] = h0;
            xo[1] = h1;
        }
        for (int j = 0; j < 2; j++) {
            int e = warp * 2 + j;
            const float* g = g_gwn + e * D_DIM;
            float d = 0.f;
            for (int i = lane; i < D_DIM; i += 32) d += sx[i] * g[i];
            for (int o = 16; o; o >>= 1) d += __shfl_down_sync(0xFFFFFFFFu, d, o);
            if (lane == 0) slog[e] = d;
        }
        __syncthreads();
        if (t == 0) {
            float ssq = 0.f;
            for (int i = 0; i < 8; i++) ssq += red[i];
            float inv = 1.0f / fmaxf(sqrtf(ssq), 1e-12f);
            float sc[E_NUM];
            for (int e = 0; e < E_NUM; e++) sc[e] = slog[e] * inv;
            int sel[KSEL]; float sw[KSEL]; float wsum = 0.f;
            for (int k = 0; k < KSEL; k++) {
                int bi = 0; float bv = -1e30f;
                for (int e = 0; e < E_NUM; e++)
                    if (sc[e] > bv) { bv = sc[e]; bi = e; }
                sel[k] = bi;
                float s = 1.0f / (1.0f + __expf(-bv));
                sw[k] = s; wsum += s; sc[bi] = -1e30f;
            }
            float invw = 1.0f / wsum;
            for (int k = 0; k < KSEL; k++) {
                g_idx[n * KSEL + k] = sel[k];
                g_w[n * KSEL + k]   = sw[k] * invw;
                atomicAdd(&g_cnt[sel[k]], 1);
            }
        }
        return;
    }

    const int p = bid - NTOK;
    const int z = p >> 9;
    const int ct = p & 31;
    const int rt = (p >> 5) & 15;

    const float* src; __half* dst;
    int mul, add;
    size_t bi, bo;
    if (z < 16)       { int e = z;      src = wg;  dst = wguT;  mul = 2; add = 0; bi = (size_t)e * D_DIM * H_DIM; bo = bi * 2; }
    else if (z < 32)  { int e = z - 16; src = wu;  dst = wguT;  mul = 2; add = 1; bi = (size_t)e * D_DIM * H_DIM; bo = bi * 2; }
    else if (z == 32) { src = swg; dst = swguT; mul = 2; add = 0; bi = 0; bo = 0; }
    else              { src = swu; dst = swguT; mul = 2; add = 1; bi = 0; bo = 0; }

    const int c0 = ct * 32, r0 = rt * 64;
    if (c0 >= H_DIM || r0 >= D_DIM) return;

    __shared__ float tile[32 * 65];
    tile_transpose(src, dst, D_DIM, H_DIM, mul, add, bi, bo, c0, r0, tile, t);
}

// scatter with in-block prefix over g_cnt
__global__ void scatter_kernel() {
    __shared__ int soff[E_NUM];
    int t = threadIdx.x;
    if (t == 0) {
        int a = 0;
        for (int e = 0; e < E_NUM; e++) { soff[e] = a; a += g_cnt[e]; }
    }
    __syncthreads();
    int id = blockIdx.x * 256 + t;
    if (id < NK) {
        int e = g_idx[id];
        int p = soff[e] + atomicAdd(&g_pos[e], 1);
        g_tok[p] = id / KSEL;
        g_tw[p]  = g_w[id];
        g_pmap[id] = p;
    }
}

// ---------------------------------------------------------------------------
// fp16 mma.sync GEMM (best geometry): block 128x128, BK=64, warp grid 2x4,
// m16n8k16, 3-stage cp.async (max slack), fragment ping-pong, 2 CTAs/SM.
// z<16 routed, z==16 shared. GU only: z==17 = w_down/sw_down transpose slice.
// ALL outputs fp16 now (shared down -> g_ysh; combine writes out once).
// ---------------------------------------------------------------------------
#define ROWB    144
#define TILE_HB (128 * ROWB)
#define NSTG    3
#define SMEM_BYTES (2 * NSTG * TILE_HB + 1024)

template <bool GU>
__global__ void __launch_bounds__(256)
mma_gemm(const __half* __restrict__ Art, const __half* __restrict__ Ash,
         const __half* __restrict__ Brt, const __half* __restrict__ Bsh,
         __half* __restrict__ outRt, __half* __restrict__ outSh,
         const float* __restrict__ wdsrc, const float* __restrict__ swdsrc,
         __half* __restrict__ wdTd, __half* __restrict__ swdTd) {
    constexpr int KD = GU ? D_DIM : H_DIM;
    const int e = blockIdx.z;
    const int t = threadIdx.x;

    extern __shared__ char smc[];

    if (GU && e == E_NUM + 1) {
        float* tile = (float*)smc;
        const int base = (blockIdx.y * 32 + blockIdx.x) * 17;
#pragma unroll 1
        for (int j = 0; j < 17; j++) {
            const int job = base + j;
            const float* src; __half* dst;
            size_t bi;
            int rem;
            if (job < 4096) { int ex = job >> 8; rem = job & 255; src = wdsrc; dst = wdTd;
                              bi = (size_t)ex * H_DIM * D_DIM; }
            else            { rem = job - 4096; src = swdsrc; dst = swdTd; bi = 0; }
            const int c0 = (rem & 31) * 32;
            const int r0 = (rem >> 5) * 64;
            tile_transpose(src, dst, H_DIM, D_DIM, 1, 0, bi, bi, c0, r0, tile, t);
        }
        return;
    }

    const bool gather = (e < E_NUM);
    const int cnt = gather ? g_cnt[e] : NTOK;
    const int m0  = blockIdx.x * 128;
    if (m0 >= cnt) return;
    int offr = 0;
    if (gather) {
        for (int q = 0; q < E_NUM; q++) offr += (q < e) ? g_cnt[q] : 0;
    }
    const int n0 = blockIdx.y * 128;

    const __half* A = gather ? Art : Ash;
    const __half* B = gather ? (Brt + (size_t)e * 1024 * KD) : Bsh;

    const uint32_t uA = smem_u32(smc);
    const uint32_t uB = uA + NSTG * TILE_HB;
    int*   rtok = (int*)(smc + 2 * NSTG * TILE_HB);
    float* twsh = (float*)(smc + 2 * NSTG * TILE_HB + 512);

    const int warp = t >> 5, lane = t & 31;
    const int wm = warp >> 2, wn = warp & 3;

    if (t < 128) {
        int gm = m0 + t;
        int cg = (gm < cnt) ? gm : 0;
        int src;
        if (GU) src = gather ? g_tok[offr + cg] : gm;
        else    src = gather ? (offr + gm) : gm;
        rtok[t] = src;
        twsh[t] = (GU && gather) ? g_tw[offr + cg] : 1.0f;
    }
    __syncthreads();

    const __half* aP[4];
    const __half* bP[4];
    uint32_t sOff[4];
#pragma unroll
    for (int j = 0; j < 4; j++) {
        int cidx = t + j * 256;
        int row = cidx >> 3, kc = cidx & 7;
        aP[j] = A + (size_t)rtok[row] * KD + kc * 8;
        bP[j] = B + (size_t)(n0 + row) * KD + kc * 8;
        sOff[j] = (uint32_t)(row * ROWB + kc * 16);
    }

    const uint32_t aRow = wm * 64 + (lane & 7) + ((lane >> 3) & 1) * 8;
    const uint32_t aCol = (lane >> 4) * 16;
    const uint32_t bRow0 = wn * 32 + ((lane >> 4) & 1) * 8 + (lane & 7);
    const uint32_t bCol = ((lane >> 3) & 1) * 16;

#define LOADSTAGE(s, k0) do {                                       \
        _Pragma("unroll")                                           \
        for (int j = 0; j < 4; j++) {                               \
            cp16(uA + (s) * TILE_HB + sOff[j], aP[j] + (k0));       \
            cp16(uB + (s) * TILE_HB + sOff[j], bP[j] + (k0));       \
        }                                                           \
    } while (0)

#define LOADFRAG(q, uAs, uBs, ks) do {                                            \
        _Pragma("unroll")                                                         \
        for (int mt = 0; mt < 4; mt++) {                                          \
            uint32_t ad = (uAs) + (aRow + mt * 16) * ROWB + (ks) * 32 + aCol;     \
            ldm4(afr[q][mt][0], afr[q][mt][1], afr[q][mt][2], afr[q][mt][3], ad); \
        }                                                                         \
        _Pragma("unroll")                                                         \
        for (int p = 0; p < 2; p++) {                                             \
            uint32_t ad = (uBs) + (bRow0 + p * 16) * ROWB + (ks) * 32 + bCol;     \
            ldm4(bfr[q][p][0], bfr[q][p][1], bfr[q][p][2], bfr[q][p][3], ad);     \
        }                                                                         \
    } while (0)

    float c[4][4][4] = {};
    uint32_t afr[2][4][4], bfr[2][2][4];

    const int NIT = KD / 64;
    LOADSTAGE(0, 0);  CP_COMMIT();
    LOADSTAGE(1, 64); CP_COMMIT();

    for (int i = 0; i < NIT; i++) {
        __syncthreads();                 // all warps done reading stage (i+2)%3 (chunk i-1)
        const int ld = i + 2;
        if (ld < NIT) { LOADSTAGE(ld % NSTG, ld * 64); }
        CP_COMMIT();
        CP_WAIT2();                      // chunk i complete; i+1, i+2 stay pending
        __syncthreads();                 // publish stage i%3

        const int s = i % NSTG;
        const uint32_t uAs = uA + s * TILE_HB;
        const uint32_t uBs = uB + s * TILE_HB;

        LOADFRAG(0, uAs, uBs, 0);
#pragma unroll
        for (int ks = 0; ks < 4; ks++) {
            const int cur = ks & 1;
            if (ks < 3) LOADFRAG(cur ^ 1, uAs, uBs, ks + 1);
#pragma unroll
            for (int mt = 0; mt < 4; mt++) {
#pragma unroll
                for (int nt = 0; nt < 4; nt++)
                    mma16(c[mt][nt], afr[cur][mt],
                          bfr[cur][nt >> 1][2 * (nt & 1)], bfr[cur][nt >> 1][2 * (nt & 1) + 1]);
            }
        }
    }
#undef LOADSTAGE
#undef LOADFRAG

#pragma unroll
    for (int mt = 0; mt < 4; mt++) {
        int r0 = wm * 64 + mt * 16 + (lane >> 2);
#pragma unroll
        for (int pass = 0; pass < 2; pass++) {
            int r = r0 + pass * 8;
            int gm = m0 + r;
            if (gm < cnt) {
                if (GU) {
                    float tw = twsh[r];
                    __half* orow = (gather ? outRt + (size_t)(offr + gm) * H_DIM
                                           : outSh + (size_t)gm * H_DIM);
#pragma unroll
                    for (int nt = 0; nt < 4; nt++) {
                        float g = c[mt][nt][pass * 2];
                        float u = c[mt][nt][pass * 2 + 1];
                        int h = (n0 + wn * 32 + nt * 8) / 2 + (lane & 3);
                        orow[h] = __float2half_rn(tw * u * g / (1.0f + __expf(-g)));
                    }
                } else {
                    __half* orow = (gather ? outRt + (size_t)(offr + gm) * D_DIM
                                           : outSh + (size_t)gm * D_DIM);
#pragma unroll
                    for (int nt = 0; nt < 4; nt++) {
                        int n = n0 + wn * 32 + nt * 8 + 2 * (lane & 3);
                        *(__half2*)(orow + n) =
                            __floats2half2_rn(c[mt][nt][pass * 2], c[mt][nt][pass * 2 + 1]);
                    }
                }
            }
        }
    }
}

// ---------------------------------------------------------------------------
// combine: out[n] = g_ysh[n] + sum_k g_yh[pmap[n,k]]   (single fp32 write)
// ---------------------------------------------------------------------------
__global__ void combine_kernel(float* __restrict__ out) {
    const int n = blockIdx.x, t = threadIdx.x;
    __shared__ int pm[KSEL];
    if (t < KSEL) pm[t] = g_pmap[n * KSEL + t];
    __syncthreads();
    const __half2* sh = (const __half2*)(g_ysh + (size_t)n * D_DIM + t * 4);
    float2 s0 = __half22float2(sh[0]);
    float2 s1 = __half22float2(sh[1]);
    float4 acc = make_float4(s0.x, s0.y, s1.x, s1.y);
#pragma unroll
    for (int k = 0; k < KSEL; k++) {
        const __half2* p = (const __half2*)(g_yh + (size_t)pm[k] * D_DIM + t * 4);
        float2 v0 = __half22float2(p[0]);
        float2 v1 = __half22float2(p[1]);
        acc.x += v0.x; acc.y += v0.y; acc.z += v1.x; acc.w += v1.y;
    }
    *(float4*)(out + (size_t)n * D_DIM + t * 4) = acc;
}

// ---------------------------------------------------------------------------
// Launch:  gwnorm(1) fused_pg(2) scatter(3) GU(4, incl wd-prep) DN(5) combine(6)
// ---------------------------------------------------------------------------
extern "C" void kernel_launch(void* const* d_in, const int* in_sizes, int n_in,
                              void* d_out, int out_size) {
    (void)in_sizes; (void)n_in; (void)out_size;
    const float* x       = (const float*)d_in[0];
    const float* gate_w  = (const float*)d_in[1];
    const float* w_gate  = (const float*)d_in[2];
    const float* w_up    = (const float*)d_in[3];
    const float* w_down  = (const float*)d_in[4];
    const float* sw_gate = (const float*)d_in[5];
    const float* sw_up   = (const float*)d_in[6];
    const float* sw_down = (const float*)d_in[7];
    float* out = (float*)d_out;

    cudaFuncSetAttribute(mma_gemm<true>,  cudaFuncAttributeMaxDynamicSharedMemorySize, SMEM_BYTES);
    cudaFuncSetAttribute(mma_gemm<false>, cudaFuncAttributeMaxDynamicSharedMemorySize, SMEM_BYTES);

    __half* xt; __half* wguT; __half* wdT; __half* swguT; __half* swdT;
    __half* hbuf; __half* hsbuf; __half* ybuf; __half* yshbuf;
    cudaGetSymbolAddress((void**)&xt,     g_xt);
    cudaGetSymbolAddress((void**)&wguT,   g_wguT);
    cudaGetSymbolAddress((void**)&wdT,    g_wdT);
    cudaGetSymbolAddress((void**)&swguT,  g_swguT);
    cudaGetSymbolAddress((void**)&swdT,   g_swdT);
    cudaGetSymbolAddress((void**)&hbuf,   g_h);
    cudaGetSymbolAddress((void**)&hsbuf,  g_hs);
    cudaGetSymbolAddress((void**)&ybuf,   g_yh);
    cudaGetSymbolAddress((void**)&yshbuf, g_ysh);

    gwnorm_kernel<<<E_NUM, 256>>>(gate_w);

    fused_pg_kernel<<<NTOK + 34 * 512, 256>>>(
        x, w_gate, w_up, sw_gate, sw_up, wguT, swguT);

    scatter_kernel<<<(NK + 255) / 256, 256>>>();

    // GU: routed (z<16) + shared (z==16) + w_down prep slice (z==17)
    mma_gemm<true><<<dim3(32, 8, E_NUM + 2), 256, SMEM_BYTES>>>(
        xt, xt, wguT, swguT, hbuf, hsbuf, w_down, sw_down, wdT, swdT);

    // DN: routed -> g_yh (fp16), shared -> g_ysh (fp16)
    mma_gemm<false><<<dim3(32, 8, E_NUM + 1), 256, SMEM_BYTES>>>(
        hbuf, hsbuf, wdT, swdT, ybuf, yshbuf, nullptr, nullptr, nullptr, nullptr);

    // single fp32 write of out
    combine_kernel<<<NTOK, 256>>>(out);
}